// round 10
// baseline (speedup 1.0000x reference)
#include <cuda_runtime.h>
#include <cstdint>

// out[b, l] = x[b, perm[b, l]]   (B=1024, L=16384)
// 2-CTA cluster per row with TMA MULTICAST cooperative slicing:
// each CTA of the pair bulk-loads a DIFFERENT 32KB half of the row and
// multicasts it to both CTAs' SMEM -> the row crosses GMEM->SMEM exactly
// once (R8 read it twice). Each CTA then gathers/stores its half of out.

#define THREADS 512
#define CSIZE 2

__global__ __launch_bounds__(THREADS, 3) __cluster_dims__(CSIZE, 1, 1)
void interleave_mcast_kernel(const float* __restrict__ x,
                             const int* __restrict__ perm,
                             float* __restrict__ out,
                             int L) {
    extern __shared__ __align__(128) unsigned char smem_raw[];
    float* srow = reinterpret_cast<float*>(smem_raw);
    uint64_t* mbar_p = reinterpret_cast<uint64_t*>(smem_raw + (size_t)L * sizeof(float));
    uint32_t mbar = (uint32_t)__cvta_generic_to_shared(mbar_p);

    uint32_t rank;
    asm("mov.u32 %0, %%cluster_ctarank;" : "=r"(rank));

    long long row = blockIdx.x >> 1;
    int half = blockIdx.x & 1;              // == rank (cluster packs adjacent bids)
    int H = L >> 1;                          // 8192 elements per half
    long long base = row * (long long)L + (long long)half * H;

    const float* xrow  = x + row * (long long)L;
    const int*   phalf = perm + base;
    float*       ohalf = out + base;

    int tid = threadIdx.x;
    unsigned row_bytes   = (unsigned)L * 4u;       // 64 KB (full row, expect_tx)
    unsigned slice_bytes = (unsigned)H * 4u;       // 32 KB (this CTA's TMA slice)

    if (tid == 0) {
        asm volatile("mbarrier.init.shared.b64 [%0], %1;"
                     :: "r"(mbar), "r"(1) : "memory");
    }
    __syncthreads();

    // All cluster mbarriers initialized before any multicast targets them.
    asm volatile("barrier.cluster.arrive.aligned;" ::: "memory");
    asm volatile("barrier.cluster.wait.aligned;" ::: "memory");

    if (tid == 0) {
        asm volatile("mbarrier.arrive.expect_tx.shared.b64 _, [%0], %1;"
                     :: "r"(mbar), "r"(row_bytes) : "memory");
        // This CTA loads its slice (rank-th half of the row) and multicasts it
        // to the same smem offset in both CTAs.
        uint32_t sdst = (uint32_t)__cvta_generic_to_shared(srow + (int)rank * H);
        const float* src = xrow + (int)rank * H;
        uint16_t mask = (1u << CSIZE) - 1u;
        asm volatile("cp.async.bulk.shared::cluster.global.mbarrier::complete_tx::bytes"
                     ".multicast::cluster [%0], [%1], %2, [%3], %4;"
                     :: "r"(sdst), "l"(src), "r"(slice_bytes), "r"(mbar), "h"(mask)
                     : "memory");
    }

    // Prefetch this half's perm (H/4 = 2048 = 4*THREADS int4) during the TMA.
    const int4* p4 = reinterpret_cast<const int4*>(phalf);
    int4 p[4];
    #pragma unroll
    for (int j = 0; j < 4; j++) p[j] = __ldcs(p4 + tid + j * THREADS);

    // Wait for BOTH slices (expect_tx = full row, fed by both CTAs' TMAs).
    {
        uint32_t done;
        asm volatile(
            "{\n\t.reg .pred P;\n\t"
            "mbarrier.try_wait.parity.acquire.cta.shared::cta.b64 P, [%1], %2;\n\t"
            "selp.b32 %0, 1, 0, P;\n\t}"
            : "=r"(done) : "r"(mbar), "r"(0u) : "memory");
        if (!done) {
            asm volatile(
                "{\n\t.reg .pred P;\n\t"
                "W_%=:\n\t"
                "mbarrier.try_wait.parity.acquire.cta.shared::cta.b64 P, [%0], %1, 0x989680;\n\t"
                "@P bra.uni D_%=;\n\t"
                "bra.uni W_%=;\n\t"
                "D_%=:\n\t}"
                :: "r"(mbar), "r"(0u) : "memory");
        }
    }

    // Gather from SMEM, streaming stores.
    float4* o4 = reinterpret_cast<float4*>(ohalf);
    #pragma unroll
    for (int j = 0; j < 4; j++) {
        float4 o;
        o.x = srow[p[j].x];
        o.y = srow[p[j].y];
        o.z = srow[p[j].z];
        o.w = srow[p[j].w];
        __stcs(o4 + tid + j * THREADS, o);
    }

    // No CTA may exit while its multicast into the peer may be pending.
    asm volatile("barrier.cluster.arrive.aligned;" ::: "memory");
    asm volatile("barrier.cluster.wait.aligned;" ::: "memory");
}

extern "C" void kernel_launch(void* const* d_in, const int* in_sizes, int n_in,
                              void* d_out, int out_size) {
    const float* x   = (const float*)d_in[0];
    const int* perm  = (const int*)d_in[1];
    float* out       = (float*)d_out;

    long long total = (long long)in_sizes[1];
    int B = 1024;
    int L = (int)(total / B);

    size_t smem = (size_t)L * sizeof(float) + 16;
    cudaFuncSetAttribute(interleave_mcast_kernel,
                         cudaFuncAttributeMaxDynamicSharedMemorySize, (int)smem);

    interleave_mcast_kernel<<<CSIZE * B, THREADS, smem>>>(x, perm, out, L);
}

// round 11
// speedup vs baseline: 1.1765x; 1.1765x over previous
#include <cuda_runtime.h>
#include <cstdint>

// out[b, l] = x[b, perm[b, l]]   (B=1024, L=16384)
// One CTA per row, 1024 threads, 2 CTAs/SM (100% thread occupancy).
// Full row staged via one 64KB TMA bulk load (x read exactly once per row),
// perm prefetched (int4, streaming) during the TMA, then SMEM gather +
// coalesced streaming float4 stores. Max per-SM warp count maximizes
// outstanding-store MLP feeding the DRAM write stream.

#define THREADS 1024

__global__ __launch_bounds__(THREADS, 2)
void interleave_fullocc_kernel(const float* __restrict__ x,
                               const int* __restrict__ perm,
                               float* __restrict__ out,
                               int L) {
    extern __shared__ __align__(128) unsigned char smem_raw[];
    float* srow = reinterpret_cast<float*>(smem_raw);
    uint64_t* mbar_p = reinterpret_cast<uint64_t*>(smem_raw + (size_t)L * sizeof(float));
    uint32_t mbar = (uint32_t)__cvta_generic_to_shared(mbar_p);
    uint32_t sdst = (uint32_t)__cvta_generic_to_shared(srow);

    long long row = blockIdx.x;
    const float* xrow = x + row * (long long)L;
    const int*   prow = perm + row * (long long)L;
    float*       orow = out + row * (long long)L;

    int tid = threadIdx.x;
    unsigned bytes = (unsigned)L * 4u;

    if (tid == 0) {
        asm volatile("mbarrier.init.shared.b64 [%0], %1;"
                     :: "r"(mbar), "r"(1) : "memory");
    }
    __syncthreads();

    if (tid == 0) {
        uint64_t policy;
        asm volatile("createpolicy.fractional.L2::evict_last.b64 %0, 1.0;"
                     : "=l"(policy));
        asm volatile("mbarrier.arrive.expect_tx.shared.b64 _, [%0], %1;"
                     :: "r"(mbar), "r"(bytes) : "memory");
        asm volatile("cp.async.bulk.shared::cta.global.mbarrier::complete_tx::bytes"
                     ".L2::cache_hint [%0], [%1], %2, [%3], %4;"
                     :: "r"(sdst), "l"(xrow), "r"(bytes), "r"(mbar), "l"(policy)
                     : "memory");
    }

    // Prefetch perm while the TMA streams the row.
    // L/4 = 4096 int4 = 4 * THREADS exactly.
    const int4* p4 = reinterpret_cast<const int4*>(prow);
    int4 p[4];
    #pragma unroll
    for (int j = 0; j < 4; j++) p[j] = __ldcs(p4 + tid + j * THREADS);

    // Wait for the row (acquire orders subsequent smem reads).
    {
        uint32_t done;
        asm volatile(
            "{\n\t.reg .pred P;\n\t"
            "mbarrier.try_wait.parity.acquire.cta.shared::cta.b64 P, [%1], %2;\n\t"
            "selp.b32 %0, 1, 0, P;\n\t}"
            : "=r"(done) : "r"(mbar), "r"(0u) : "memory");
        if (!done) {
            asm volatile(
                "{\n\t.reg .pred P;\n\t"
                "W_%=:\n\t"
                "mbarrier.try_wait.parity.acquire.cta.shared::cta.b64 P, [%0], %1, 0x989680;\n\t"
                "@P bra.uni D_%=;\n\t"
                "bra.uni W_%=;\n\t"
                "D_%=:\n\t}"
                :: "r"(mbar), "r"(0u) : "memory");
        }
    }

    // Gather from SMEM, coalesced streaming stores.
    float4* o4 = reinterpret_cast<float4*>(orow);
    #pragma unroll
    for (int j = 0; j < 4; j++) {
        float4 o;
        o.x = srow[p[j].x];
        o.y = srow[p[j].y];
        o.z = srow[p[j].z];
        o.w = srow[p[j].w];
        __stcs(o4 + tid + j * THREADS, o);
    }
}

extern "C" void kernel_launch(void* const* d_in, const int* in_sizes, int n_in,
                              void* d_out, int out_size) {
    const float* x   = (const float*)d_in[0];
    const int* perm  = (const int*)d_in[1];
    float* out       = (float*)d_out;

    long long total = (long long)in_sizes[1];
    int B = 1024;
    int L = (int)(total / B);

    size_t smem = (size_t)L * sizeof(float) + 16;
    cudaFuncSetAttribute(interleave_fullocc_kernel,
                         cudaFuncAttributeMaxDynamicSharedMemorySize, (int)smem);

    interleave_fullocc_kernel<<<B, THREADS, smem>>>(x, perm, out, L);
}